// round 6
// baseline (speedup 1.0000x reference)
#include <cuda_runtime.h>

// Problem constants (fixed by the reference: B=4, C=32, H=64, W=64, NW=64)
#define NW_   64
#define HW_   4096
#define C_    32
#define B_    4
#define TPB   256           // threads per block
#define PPT   4             // pixels per thread
#define TILES (HW_ / (TPB * PPT))   // 4 tiles per (b,c) image

typedef unsigned long long u64;

__device__ __forceinline__ float ex2f(float x) {
    float y;
    asm("ex2.approx.f32 %0, %1;" : "=f"(y) : "f"(x));
    return y;
}

// Packed f32x2 FMA (sm_100+; only reachable via PTX)
__device__ __forceinline__ u64 fma2(u64 a, u64 b, u64 c) {
    u64 d;
    asm("fma.rn.f32x2 %0, %1, %2, %3;" : "=l"(d) : "l"(a), "l"(b), "l"(c));
    return d;
}
__device__ __forceinline__ u64 pack2(float lo, float hi) {
    u64 d;
    asm("mov.b64 %0, {%1, %2};" : "=l"(d) : "f"(lo), "f"(hi));
    return d;
}
__device__ __forceinline__ void unpack2(u64 v, float& lo, float& hi) {
    asm("mov.b64 {%0, %1}, %2;" : "=f"(lo), "=f"(hi) : "l"(v));
}

__global__ __launch_bounds__(TPB) void cplx_rbf_kernel(
    const float* __restrict__ x_real, const float* __restrict__ x_imag,
    const float* __restrict__ w_real, const float* __restrict__ w_imag,
    const float* __restrict__ b_real, const float* __restrict__ b_imag,
    const float* __restrict__ mu_real, const float* __restrict__ mu_imag,
    const float* __restrict__ stddev,
    float* __restrict__ out)
{
    // Coefficients pre-replicated into {v,v} b64 pairs so the mainloop needs
    // zero pack instructions for loop-invariant operands.
    __shared__ ulonglong2 s_ab[NW_];   // {AA, BB}
    __shared__ ulonglong2 s_cd[NW_];   // {CC, DD}
    __shared__ ulonglong2 s_wv[NW_];   // {wr,wr}, {wi,wi}

    const int bc   = blockIdx.x >> 2;          // (b*C + c), TILES == 4
    const int tile = blockIdx.x & (TILES - 1);
    const int c    = bc & (C_ - 1);

    const int t = threadIdx.x;
    if (t < NW_) {
        const float mur = mu_real[t];
        const float mui = mu_imag[t];
        // A = -log2(e) / (2*sigma); fold log2e so exp() is a single EX2
        const float A  = -0.72134752044448169f / stddev[t];
        const float Bc = -2.0f * A * mur;
        const float Cc = -2.0f * A * mui;
        const float Dc = A * (mur * mur + mui * mui);
        s_ab[t] = make_ulonglong2(pack2(A,  A),  pack2(Bc, Bc));
        s_cd[t] = make_ulonglong2(pack2(Cc, Cc), pack2(Dc, Dc));
        const float wr = w_real[c * NW_ + t];
        const float wi = w_imag[c * NW_ + t];
        s_wv[t] = make_ulonglong2(pack2(wr, wr), pack2(wi, wi));
    }
    __syncthreads();

    const int p0   = tile * (TPB * PPT) + t * PPT;   // 4 consecutive pixels
    const int gidx = bc * HW_ + p0;                  // 16B-aligned

    const float4 xr = *reinterpret_cast<const float4*>(x_real + gidx);
    const float4 xi = *reinterpret_cast<const float4*>(x_imag + gidx);

    // s = |x|^2 per pixel, then pack everything into pixel-pair b64 operands
    const float s0 = fmaf(xr.x, xr.x, xi.x * xi.x);
    const float s1 = fmaf(xr.y, xr.y, xi.y * xi.y);
    const float s2 = fmaf(xr.z, xr.z, xi.z * xi.z);
    const float s3 = fmaf(xr.w, xr.w, xi.w * xi.w);

    const u64 s01  = pack2(s0, s1),     s23  = pack2(s2, s3);
    const u64 xr01 = pack2(xr.x, xr.y), xr23 = pack2(xr.z, xr.w);
    const u64 xi01 = pack2(xi.x, xi.y), xi23 = pack2(xi.z, xi.w);

    u64 ar01 = 0ull, ai01 = 0ull, ar23 = 0ull, ai23 = 0ull;

#pragma unroll 8
    for (int w = 0; w < NW_; ++w) {
        const ulonglong2 ab = s_ab[w];   // LDS.128 broadcast
        const ulonglong2 cd = s_cd[w];
        const ulonglong2 wv = s_wv[w];

        // arg = A*s + B*xr + C*xi + D   (3 packed FMAs per pixel pair)
        const u64 g01 = fma2(ab.x, s01, fma2(ab.y, xr01, fma2(cd.x, xi01, cd.y)));
        const u64 g23 = fma2(ab.x, s23, fma2(ab.y, xr23, fma2(cd.x, xi23, cd.y)));

        float a0, a1, a2, a3;
        unpack2(g01, a0, a1);
        unpack2(g23, a2, a3);
        const u64 e01 = pack2(ex2f(a0), ex2f(a1));
        const u64 e23 = pack2(ex2f(a2), ex2f(a3));

        ar01 = fma2(e01, wv.x, ar01);  ai01 = fma2(e01, wv.y, ai01);
        ar23 = fma2(e23, wv.x, ar23);  ai23 = fma2(e23, wv.y, ai23);
    }

    float ar0, ar1, ar2, ar3, ai0, ai1, ai2, ai3;
    unpack2(ar01, ar0, ar1);  unpack2(ar23, ar2, ar3);
    unpack2(ai01, ai0, ai1);  unpack2(ai23, ai2, ai3);

    const float br = b_real[c];
    const float bi = b_imag[c];

    // Output layout (B,C,H,W,2): real/imag interleaved -> two float4 stores
    float4* op = reinterpret_cast<float4*>(out + 2 * gidx);
    op[0] = make_float4(ar0 + br, ai0 + bi, ar1 + br, ai1 + bi);
    op[1] = make_float4(ar2 + br, ai2 + bi, ar3 + br, ai3 + bi);
}

extern "C" void kernel_launch(void* const* d_in, const int* in_sizes, int n_in,
                              void* d_out, int out_size)
{
    const float* x_real  = (const float*)d_in[0];
    const float* x_imag  = (const float*)d_in[1];
    const float* w_real  = (const float*)d_in[2];
    const float* w_imag  = (const float*)d_in[3];
    const float* b_real  = (const float*)d_in[4];
    const float* b_imag  = (const float*)d_in[5];
    const float* mu_real = (const float*)d_in[6];
    const float* mu_imag = (const float*)d_in[7];
    const float* stddev  = (const float*)d_in[8];
    float* out = (float*)d_out;

    const int grid = B_ * C_ * TILES;   // 512 blocks
    cplx_rbf_kernel<<<grid, TPB>>>(x_real, x_imag, w_real, w_imag,
                                   b_real, b_imag, mu_real, mu_imag,
                                   stddev, out);
}

// round 8
// speedup vs baseline: 1.2341x; 1.2341x over previous
#include <cuda_runtime.h>

// Problem constants (fixed by the reference: B=4, C=32, H=64, W=64, NW=64)
#define NW_   64
#define HW_   4096
#define C_    32
#define B_    4
#define TPB   256           // threads per block
#define PPT   2             // pixels per thread (lowered: 2x warps for latency hiding)
#define TILES (HW_ / (TPB * PPT))   // 8 tiles per (b,c) image

__device__ __forceinline__ float ex2f(float x) {
    float y;
    asm("ex2.approx.f32 %0, %1;" : "=f"(y) : "f"(x));
    return y;
}

__global__ __launch_bounds__(TPB) void cplx_rbf_kernel(
    const float* __restrict__ x_real, const float* __restrict__ x_imag,
    const float* __restrict__ w_real, const float* __restrict__ w_imag,
    const float* __restrict__ b_real, const float* __restrict__ b_imag,
    const float* __restrict__ mu_real, const float* __restrict__ mu_imag,
    const float* __restrict__ stddev,
    float* __restrict__ out)
{
    __shared__ float4 s_coef[NW_];   // {A, B, C, D} per center
    __shared__ float2 s_w[NW_];      // {wr, wi} per center (one LDS.64)

    const int bc   = blockIdx.x >> 3;            // (b*C + c), TILES == 8
    const int tile = blockIdx.x & (TILES - 1);
    const int c    = bc & (C_ - 1);

    const int t = threadIdx.x;
    if (t < NW_) {
        const float mur = mu_real[t];
        const float mui = mu_imag[t];
        // A = -log2(e) / (2*sigma); fold log2e so exp() is a single EX2
        const float A = -0.72134752044448169f / stddev[t];
        s_coef[t] = make_float4(A, -2.0f * A * mur, -2.0f * A * mui,
                                A * (mur * mur + mui * mui));
        s_w[t] = make_float2(w_real[c * NW_ + t], w_imag[c * NW_ + t]);
    }
    __syncthreads();

    const int p0   = tile * (TPB * PPT) + t * PPT;   // 2 consecutive pixels
    const int gidx = bc * HW_ + p0;                  // 8B-aligned

    const float2 xr = *reinterpret_cast<const float2*>(x_real + gidx);
    const float2 xi = *reinterpret_cast<const float2*>(x_imag + gidx);

    // s = |x|^2 per pixel (computed once, reused across all 64 centers)
    const float s0 = fmaf(xr.x, xr.x, xi.x * xi.x);
    const float s1 = fmaf(xr.y, xr.y, xi.y * xi.y);

    float ar0 = 0.f, ar1 = 0.f;
    float ai0 = 0.f, ai1 = 0.f;

#pragma unroll 8
    for (int w = 0; w < NW_; ++w) {
        const float4 cf = s_coef[w];   // LDS.128 broadcast
        const float2 wv = s_w[w];      // LDS.64  broadcast

        // arg = A*s + B*xr + C*xi + D  (3 FFMA), then one EX2 per pixel
        const float e0 = ex2f(fmaf(cf.x, s0, fmaf(cf.y, xr.x, fmaf(cf.z, xi.x, cf.w))));
        const float e1 = ex2f(fmaf(cf.x, s1, fmaf(cf.y, xr.y, fmaf(cf.z, xi.y, cf.w))));

        ar0 = fmaf(e0, wv.x, ar0);  ai0 = fmaf(e0, wv.y, ai0);
        ar1 = fmaf(e1, wv.x, ar1);  ai1 = fmaf(e1, wv.y, ai1);
    }

    const float br = b_real[c];
    const float bi = b_imag[c];

    // Output layout (B,C,H,W,2): 2 pixels -> one 16B store
    float4* op = reinterpret_cast<float4*>(out + 2 * gidx);
    op[0] = make_float4(ar0 + br, ai0 + bi, ar1 + br, ai1 + bi);
}

extern "C" void kernel_launch(void* const* d_in, const int* in_sizes, int n_in,
                              void* d_out, int out_size)
{
    const float* x_real  = (const float*)d_in[0];
    const float* x_imag  = (const float*)d_in[1];
    const float* w_real  = (const float*)d_in[2];
    const float* w_imag  = (const float*)d_in[3];
    const float* b_real  = (const float*)d_in[4];
    const float* b_imag  = (const float*)d_in[5];
    const float* mu_real = (const float*)d_in[6];
    const float* mu_imag = (const float*)d_in[7];
    const float* stddev  = (const float*)d_in[8];
    float* out = (float*)d_out;

    const int grid = B_ * C_ * TILES;   // 1024 blocks
    cplx_rbf_kernel<<<grid, TPB>>>(x_real, x_imag, w_real, w_imag,
                                   b_real, b_imag, mu_real, mu_imag,
                                   stddev, out);
}